// round 6
// baseline (speedup 1.0000x reference)
#include <cuda_runtime.h>
#include <cstdint>

// Entmax (alpha=1.5) per row, B=2048 x N=32000 fp32.
// v6: persistent CTA per SM + chunked TMA triple-buffer.
//   Rows split into 2 halves of 62.5 KB; 3 smem buffers cycled round-robin,
//   2 TMA chunks always in flight -> gapless DRAM read stream. Row processed
//   register-resident: filter@rowmax-1 -> warp-0 Newton -> stcs output.

#define NC        32000
#define NV        (NC / 4)
#define NH        (NC / 2)       // floats per half-chunk (16000)
#define NVH       (NH / 4)       // float4 per half-chunk (4000)
#define TPB       1024
#define VPT       8              // float4 per thread (full row)
#define VPH       4              // float4 per thread per half
#define CAP       1024
#define NEG       (-1e30f)
#define CHUNK_BYTES (NH * 4)     // 64000
#define NBUF      3

__device__ __forceinline__ uint32_t smem_u32(const void* p) {
    uint32_t a;
    asm("{ .reg .u64 t; cvta.to.shared.u64 t, %1; cvt.u32.u64 %0, t; }"
        : "=r"(a) : "l"(p));
    return a;
}
__device__ __forceinline__ void mbar_init(uint32_t a, uint32_t cnt) {
    asm volatile("mbarrier.init.shared.b64 [%0], %1;" :: "r"(a), "r"(cnt) : "memory");
}
__device__ __forceinline__ void mbar_expect_tx(uint32_t a, uint32_t bytes) {
    asm volatile("mbarrier.arrive.expect_tx.shared.b64 _, [%0], %1;"
                 :: "r"(a), "r"(bytes) : "memory");
}
__device__ __forceinline__ void tma_bulk_g2s(uint32_t dst, const void* src,
                                             uint32_t bytes, uint32_t mbar) {
    asm volatile(
        "cp.async.bulk.shared::cta.global.mbarrier::complete_tx::bytes "
        "[%0], [%1], %2, [%3];"
        :: "r"(dst), "l"(src), "r"(bytes), "r"(mbar) : "memory");
}
#define MBAR_WAIT(mbar, parity) do { \
    asm volatile( \
        "{\n\t.reg .pred P1;\n\t" \
        "WAIT_LOOP_%=:\n\t" \
        "mbarrier.try_wait.parity.acquire.cta.shared::cta.b64 P1, [%0], %1, 0x989680;\n\t" \
        "@P1 bra.uni WAIT_DONE_%=;\n\t" \
        "bra.uni WAIT_LOOP_%=;\n\t" \
        "WAIT_DONE_%=:\n\t}" \
        :: "r"(mbar), "r"(parity) : "memory"); \
} while (0)

__global__ __launch_bounds__(TPB, 1)
void entmax_kernel(const float* __restrict__ z, float* __restrict__ out,
                   int rows, int gstride) {
    __shared__ float    s_f[32];
    __shared__ float    s_g[32];
    __shared__ int      s_i[32];
    __shared__ float    s_cand[CAP];
    __shared__ int      s_cnt;
    __shared__ float    s_tau0, s_vmax, s_tauref;
    __shared__ int      s_bK;
    __shared__ float    s_bS, s_bV;
    __shared__ uint64_t s_mbars[NBUF];
    extern __shared__ float4 s_buf[];          // NBUF * NVH float4 = 187.5 KB

    const int tid  = threadIdx.x;
    const int lane = tid & 31;
    const int wid  = tid >> 5;

    uint32_t mb[NBUF];
    #pragma unroll
    for (int b = 0; b < NBUF; ++b) mb[b] = smem_u32(&s_mbars[b]);
    const uint32_t bufa = smem_u32(s_buf);

    if (tid == 0) {
        #pragma unroll
        for (int b = 0; b < NBUF; ++b) mbar_init(mb[b], 1);
    }
    __syncthreads();

    const int r0 = blockIdx.x;
    const int myrows  = (r0 < rows) ? ((rows - r0 - 1) / gstride + 1) : 0;
    const int nchunks = myrows * 2;
    // chunk t: row r0 + (t>>1)*gstride, half t&1

    if (tid == 0) {
        #pragma unroll
        for (int t = 0; t < NBUF; ++t) {
            if (t < nchunks) {
                const long long src = (long long)(r0 + (t >> 1) * gstride) * NC
                                    + (long long)(t & 1) * NH;
                mbar_expect_tx(mb[t], CHUNK_BYTES);
                tma_bulk_g2s(bufa + (uint32_t)t * CHUNK_BYTES, z + src,
                             CHUNK_BYTES, mb[t]);
            }
        }
    }

    int t = 0;
    for (int ri = 0; ri < myrows; ++ri) {
        const int row = r0 + ri * gstride;

        // ---- consume two half-chunks into registers (+ local max) ----
        float4 r[VPT];
        float lmax = NEG;
        #pragma unroll
        for (int h = 0; h < 2; ++h, ++t) {
            const int b = t % NBUF;
            MBAR_WAIT(mb[b], (uint32_t)((t / NBUF) & 1));
            const float4* buf = s_buf + b * NVH;
            #pragma unroll
            for (int j = 0; j < VPH; ++j) {
                const int f = tid + j * TPB;
                const int slot = h * VPH + j;
                if (f < NVH) {
                    float4 v = buf[f];
                    r[slot] = v;
                    lmax = fmaxf(lmax, fmaxf(fmaxf(v.x, v.y), fmaxf(v.z, v.w)));
                } else {
                    r[slot] = make_float4(NEG, NEG, NEG, NEG);
                }
            }
            __syncthreads();          // all reads of buf b done
            if (tid == 0) {
                asm volatile("fence.proxy.async.shared::cta;" ::: "memory");
                const int nxt = t + NBUF;
                if (nxt < nchunks) {
                    const long long src = (long long)(r0 + (nxt >> 1) * gstride) * NC
                                        + (long long)(nxt & 1) * NH;
                    mbar_expect_tx(mb[b], CHUNK_BYTES);
                    tma_bulk_g2s(bufa + (uint32_t)b * CHUNK_BYTES, z + src,
                                 CHUNK_BYTES, mb[b]);
                }
                if (h == 0) s_cnt = 0;
            }
        }

        // ---- block max reduce -> tau0 = rowmax - 1 ----
        #pragma unroll
        for (int o = 16; o; o >>= 1)
            lmax = fmaxf(lmax, __shfl_xor_sync(0xffffffffu, lmax, o));
        if (lane == 0) s_f[wid] = lmax;
        __syncthreads();              // also publishes s_cnt = 0
        if (tid < 32) {
            float m = s_f[tid];
            #pragma unroll
            for (int o = 16; o; o >>= 1)
                m = fmaxf(m, __shfl_xor_sync(0xffffffffu, m, o));
            if (tid == 0) s_tau0 = m - 1.0f;
        }
        __syncthreads();
        const float tau0 = s_tau0;

        // ---- filter: candidates z > tau0 (tau0 <= tau*: support-complete) ----
        float vmax = NEG;
        #pragma unroll
        for (int j = 0; j < VPT; ++j) {
            float c;
            c = r[j].x; if (c > tau0) { int p = atomicAdd(&s_cnt, 1); if (p < CAP) s_cand[p] = c; } else vmax = fmaxf(vmax, c);
            c = r[j].y; if (c > tau0) { int p = atomicAdd(&s_cnt, 1); if (p < CAP) s_cand[p] = c; } else vmax = fmaxf(vmax, c);
            c = r[j].z; if (c > tau0) { int p = atomicAdd(&s_cnt, 1); if (p < CAP) s_cand[p] = c; } else vmax = fmaxf(vmax, c);
            c = r[j].w; if (c > tau0) { int p = atomicAdd(&s_cnt, 1); if (p < CAP) s_cand[p] = c; } else vmax = fmaxf(vmax, c);
        }
        #pragma unroll
        for (int o = 16; o; o >>= 1)
            vmax = fmaxf(vmax, __shfl_xor_sync(0xffffffffu, vmax, o));
        if (lane == 0) s_g[wid] = vmax;
        __syncthreads();
        if (tid < 32) {
            float m = s_g[tid];
            #pragma unroll
            for (int o = 16; o; o >>= 1)
                m = fmaxf(m, __shfl_xor_sync(0xffffffffu, m, o));
            if (tid == 0) s_vmax = m;
        }
        __syncthreads();
        const int cnt = s_cnt;
        float tau_ref;

        if (cnt <= CAP) {
            // ---- fast path: warp 0 Newton on the candidate set ----
            if (wid == 0) {
                float tl = tau0;
                int   kp = -1;
                int   kF = 1; float SF = 0.0f; float vcF = NEG;
                for (int itr = 0; itr < 64; ++itr) {
                    int k = 0; float S = 0.0f; float vc = NEG;
                    for (int i = lane; i < cnt; i += 32) {
                        const float c = s_cand[i];
                        if (c > tl) { k++; S += c; } else vc = fmaxf(vc, c);
                    }
                    #pragma unroll
                    for (int o = 16; o; o >>= 1) {
                        k += __shfl_xor_sync(0xffffffffu, k, o);
                        S += __shfl_xor_sync(0xffffffffu, S, o);
                        vc = fmaxf(vc, __shfl_xor_sync(0xffffffffu, vc, o));
                    }
                    kF = k; SF = S; vcF = vc;
                    if (k == kp) break;           // support fixed point
                    kp = k;
                    tl = (S - 1.0f) / (float)k;
                }
                // reference quirk: cs[k_max] = S + max{z <= tau_final}
                const float vfin = fmaxf(vcF, s_vmax);
                const float vt = (vfin > -1e29f) ? vfin : 0.0f;
                if (lane == 0) s_tauref = (SF + vt - 1.0f) / (float)kF;
            }
            __syncthreads();
            tau_ref = s_tauref;
        } else {
            // ---- fallback: block-wide Newton over register data ----
            float tau = tau0;
            int kprev = -1;
            tau_ref = 0.0f;
            for (int it = 0; it < 64; ++it) {
                int k = 0; float S = 0.0f; float v = NEG;
                #pragma unroll
                for (int j = 0; j < VPT; ++j) {
                    float c;
                    c = r[j].x; if (c > tau) { k++; S += c; } else v = fmaxf(v, c);
                    c = r[j].y; if (c > tau) { k++; S += c; } else v = fmaxf(v, c);
                    c = r[j].z; if (c > tau) { k++; S += c; } else v = fmaxf(v, c);
                    c = r[j].w; if (c > tau) { k++; S += c; } else v = fmaxf(v, c);
                }
                #pragma unroll
                for (int o = 16; o; o >>= 1) {
                    k += __shfl_xor_sync(0xffffffffu, k, o);
                    S += __shfl_xor_sync(0xffffffffu, S, o);
                    v  = fmaxf(v, __shfl_xor_sync(0xffffffffu, v, o));
                }
                if (lane == 0) { s_i[wid] = k; s_f[wid] = S; s_g[wid] = v; }
                __syncthreads();
                if (tid < 32) {
                    int kk = s_i[tid]; float SS = s_f[tid]; float vv = s_g[tid];
                    #pragma unroll
                    for (int o = 16; o; o >>= 1) {
                        kk += __shfl_xor_sync(0xffffffffu, kk, o);
                        SS += __shfl_xor_sync(0xffffffffu, SS, o);
                        vv  = fmaxf(vv, __shfl_xor_sync(0xffffffffu, vv, o));
                    }
                    if (tid == 0) { s_bK = kk; s_bS = SS; s_bV = vv; }
                }
                __syncthreads();
                const int   K  = s_bK;
                const float Sa = s_bS;
                const float Va = s_bV;
                if (K == kprev || it == 63) {
                    const float vt = (Va > -1e29f) ? Va : 0.0f;
                    tau_ref = (Sa + vt - 1.0f) / (float)K;
                    break;
                }
                kprev = K;
                tau = (Sa - 1.0f) / (float)K;
                __syncthreads();
            }
        }

        // ---- output: relu(z - tau_ref)^1.5 from registers ----
        float4* orow = (float4*)(out + (long long)row * NC);
        #pragma unroll
        for (int h = 0; h < 2; ++h) {
            #pragma unroll
            for (int j = 0; j < VPH; ++j) {
                const int f = tid + j * TPB;
                if (f < NVH) {
                    const float4 v = r[h * VPH + j];
                    float a = v.x - tau_ref;
                    float b = v.y - tau_ref;
                    float c = v.z - tau_ref;
                    float d = v.w - tau_ref;
                    float4 o;
                    if (fmaxf(fmaxf(a, b), fmaxf(c, d)) > 0.0f) {
                        a = fmaxf(a, 0.0f); b = fmaxf(b, 0.0f);
                        c = fmaxf(c, 0.0f); d = fmaxf(d, 0.0f);
                        o.x = a * sqrtf(a);
                        o.y = b * sqrtf(b);
                        o.z = c * sqrtf(c);
                        o.w = d * sqrtf(d);
                    } else {
                        o.x = 0.0f; o.y = 0.0f; o.z = 0.0f; o.w = 0.0f;
                    }
                    __stcs(&orow[h * NVH + f], o);
                }
            }
        }
    }
}

extern "C" void kernel_launch(void* const* d_in, const int* in_sizes, int n_in,
                              void* d_out, int out_size) {
    const float* z = (const float*)d_in[0];
    float* out = (float*)d_out;
    const int rows = in_sizes[0] / NC;

    int dev = 0, sms = 148;
    cudaGetDevice(&dev);
    cudaDeviceGetAttribute(&sms, cudaDevAttrMultiProcessorCount, dev);
    cudaFuncSetAttribute(entmax_kernel,
                         cudaFuncAttributeMaxDynamicSharedMemorySize,
                         NBUF * CHUNK_BYTES);

    const int grid = (rows < sms) ? rows : sms;
    entmax_kernel<<<grid, TPB, NBUF * CHUNK_BYTES>>>(z, out, rows, grid);
}

// round 8
// speedup vs baseline: 1.2260x; 1.2260x over previous
#include <cuda_runtime.h>
#include <cstdint>

// Entmax (alpha=1.5) per row, B=2048 x N=32000 fp32.
// v7 = v5 (persistent CTA + single-buffer TMA double-buffer-in-time, phase-
// disjoint smem usage) with reduction barriers cut 6 -> 4 per row:
//   - all warps redundantly reduce the max partials (no 2nd stage sync)
//   - warp 0 privately reduces vmax partials inside its Newton section
// Lesson from v6: TMA smem writes must NOT overlap the LDS copy (shared port).

#define NC        32000
#define NV        (NC / 4)
#define TPB       1024
#define VPT       8
#define CAP       1024
#define NEG       (-1e30f)
#define ROW_BYTES (NC * 4)

__device__ __forceinline__ uint32_t smem_u32(const void* p) {
    uint32_t a;
    asm("{ .reg .u64 t; cvta.to.shared.u64 t, %1; cvt.u32.u64 %0, t; }"
        : "=r"(a) : "l"(p));
    return a;
}
__device__ __forceinline__ void mbar_init(uint32_t a, uint32_t cnt) {
    asm volatile("mbarrier.init.shared.b64 [%0], %1;" :: "r"(a), "r"(cnt) : "memory");
}
__device__ __forceinline__ void mbar_expect_tx(uint32_t a, uint32_t bytes) {
    asm volatile("mbarrier.arrive.expect_tx.shared.b64 _, [%0], %1;"
                 :: "r"(a), "r"(bytes) : "memory");
}
__device__ __forceinline__ void tma_bulk_g2s(uint32_t dst, const void* src,
                                             uint32_t bytes, uint32_t mbar) {
    asm volatile(
        "cp.async.bulk.shared::cta.global.mbarrier::complete_tx::bytes "
        "[%0], [%1], %2, [%3];"
        :: "r"(dst), "l"(src), "r"(bytes), "r"(mbar) : "memory");
}
#define MBAR_WAIT(mbar, parity) do { \
    asm volatile( \
        "{\n\t.reg .pred P1;\n\t" \
        "WAIT_LOOP_%=:\n\t" \
        "mbarrier.try_wait.parity.acquire.cta.shared::cta.b64 P1, [%0], %1, 0x989680;\n\t" \
        "@P1 bra.uni WAIT_DONE_%=;\n\t" \
        "bra.uni WAIT_LOOP_%=;\n\t" \
        "WAIT_DONE_%=:\n\t}" \
        :: "r"(mbar), "r"(parity) : "memory"); \
} while (0)

__global__ __launch_bounds__(TPB, 1)
void entmax_kernel(const float* __restrict__ z, float* __restrict__ out,
                   int rows, int gstride) {
    __shared__ float    s_f[32];      // max partials
    __shared__ float    s_g[32];      // vmax partials
    __shared__ int      s_i[32];      // fallback count partials
    __shared__ float    s_h[32];      // fallback sum partials
    __shared__ float    s_cand[CAP];
    __shared__ int      s_cnt;
    __shared__ float    s_tauref;
    __shared__ int      s_bK;
    __shared__ float    s_bS, s_bV;
    __shared__ uint64_t s_mbar;
    extern __shared__ float4 s_buf[];            // NV float4 = 125 KB

    const int tid  = threadIdx.x;
    const int lane = tid & 31;
    const int wid  = tid >> 5;

    const uint32_t mbar = smem_u32(&s_mbar);
    const uint32_t bufa = smem_u32(s_buf);
    if (tid == 0) mbar_init(mbar, 1);
    __syncthreads();

    const int r0 = blockIdx.x;
    if (r0 < rows && tid == 0) {
        mbar_expect_tx(mbar, ROW_BYTES);
        tma_bulk_g2s(bufa, z + (long long)r0 * NC, ROW_BYTES, mbar);
    }

    uint32_t phase = 0;
    for (int row = r0; row < rows; row += gstride) {
        // ---- wait for row data; copy smem -> regs fused with local max ----
        MBAR_WAIT(mbar, phase);
        phase ^= 1;

        float4 r[VPT];
        float lmax = NEG;
        #pragma unroll
        for (int j = 0; j < VPT; ++j) {
            const int f = tid + j * TPB;
            if (f < NV) {
                float4 v = s_buf[f];
                r[j] = v;
                lmax = fmaxf(lmax, fmaxf(fmaxf(v.x, v.y), fmaxf(v.z, v.w)));
            } else {
                r[j] = make_float4(NEG, NEG, NEG, NEG);
            }
        }
        __syncthreads();               // (1) all smem reads of s_buf done

        // ---- issue next row's TMA; runs during compute (smem-idle) phases --
        if (tid == 0) {
            asm volatile("fence.proxy.async.shared::cta;" ::: "memory");
            const int nxt = row + gstride;
            if (nxt < rows) {
                mbar_expect_tx(mbar, ROW_BYTES);
                tma_bulk_g2s(bufa, z + (long long)nxt * NC, ROW_BYTES, mbar);
            }
            s_cnt = 0;
        }

        // ---- max reduce: publish warp partials once; every warp reduces the
        // 32 partials itself -> tau0 known block-wide after ONE sync ----
        #pragma unroll
        for (int o = 16; o; o >>= 1)
            lmax = fmaxf(lmax, __shfl_xor_sync(0xffffffffu, lmax, o));
        if (lane == 0) s_f[wid] = lmax;
        __syncthreads();               // (2) partials + s_cnt=0 visible
        float m = s_f[lane];
        #pragma unroll
        for (int o = 16; o; o >>= 1)
            m = fmaxf(m, __shfl_xor_sync(0xffffffffu, m, o));
        const float tau0 = m - 1.0f;   // uniform across block

        // ---- filter: candidates z > tau0 (tau0 <= tau*: support-complete) --
        float vmax = NEG;
        #pragma unroll
        for (int j = 0; j < VPT; ++j) {
            float c;
            c = r[j].x; if (c > tau0) { int p = atomicAdd(&s_cnt, 1); if (p < CAP) s_cand[p] = c; } else vmax = fmaxf(vmax, c);
            c = r[j].y; if (c > tau0) { int p = atomicAdd(&s_cnt, 1); if (p < CAP) s_cand[p] = c; } else vmax = fmaxf(vmax, c);
            c = r[j].z; if (c > tau0) { int p = atomicAdd(&s_cnt, 1); if (p < CAP) s_cand[p] = c; } else vmax = fmaxf(vmax, c);
            c = r[j].w; if (c > tau0) { int p = atomicAdd(&s_cnt, 1); if (p < CAP) s_cand[p] = c; } else vmax = fmaxf(vmax, c);
        }
        #pragma unroll
        for (int o = 16; o; o >>= 1)
            vmax = fmaxf(vmax, __shfl_xor_sync(0xffffffffu, vmax, o));
        if (lane == 0) s_g[wid] = vmax;
        __syncthreads();               // (3) cand/cnt/vmax partials visible
        const int cnt = s_cnt;
        float tau_ref;

        if (cnt <= CAP) {
            // ---- warp 0: reduce vmax partials privately, then Newton ----
            if (wid == 0) {
                float gv = s_g[lane];
                #pragma unroll
                for (int o = 16; o; o >>= 1)
                    gv = fmaxf(gv, __shfl_xor_sync(0xffffffffu, gv, o));

                float tl = tau0;
                int   kp = -1;
                int   kF = 1; float SF = 0.0f; float vcF = NEG;
                for (int itr = 0; itr < 64; ++itr) {
                    int k = 0; float S = 0.0f; float vc = NEG;
                    for (int i = lane; i < cnt; i += 32) {
                        const float c = s_cand[i];
                        if (c > tl) { k++; S += c; } else vc = fmaxf(vc, c);
                    }
                    #pragma unroll
                    for (int o = 16; o; o >>= 1) {
                        k += __shfl_xor_sync(0xffffffffu, k, o);
                        S += __shfl_xor_sync(0xffffffffu, S, o);
                        vc = fmaxf(vc, __shfl_xor_sync(0xffffffffu, vc, o));
                    }
                    kF = k; SF = S; vcF = vc;
                    if (k == kp) break;           // support fixed point
                    kp = k;
                    tl = (S - 1.0f) / (float)k;
                }
                // reference quirk: cs[k_max] = S + max{z <= tau_final}
                const float vfin = fmaxf(vcF, gv);
                const float vt = (vfin > -1e29f) ? vfin : 0.0f;
                if (lane == 0) s_tauref = (SF + vt - 1.0f) / (float)kF;
            }
            __syncthreads();           // (4) tau_ref published
            tau_ref = s_tauref;
        } else {
            // ---- fallback: block-wide Newton over register data ----
            float gv = s_g[lane & 31];
            float tau = tau0;
            int kprev = -1;
            tau_ref = 0.0f;
            (void)gv;
            for (int it = 0; it < 64; ++it) {
                int k = 0; float S = 0.0f; float v = NEG;
                #pragma unroll
                for (int j = 0; j < VPT; ++j) {
                    float c;
                    c = r[j].x; if (c > tau) { k++; S += c; } else v = fmaxf(v, c);
                    c = r[j].y; if (c > tau) { k++; S += c; } else v = fmaxf(v, c);
                    c = r[j].z; if (c > tau) { k++; S += c; } else v = fmaxf(v, c);
                    c = r[j].w; if (c > tau) { k++; S += c; } else v = fmaxf(v, c);
                }
                #pragma unroll
                for (int o = 16; o; o >>= 1) {
                    k += __shfl_xor_sync(0xffffffffu, k, o);
                    S += __shfl_xor_sync(0xffffffffu, S, o);
                    v  = fmaxf(v, __shfl_xor_sync(0xffffffffu, v, o));
                }
                if (lane == 0) { s_i[wid] = k; s_h[wid] = S; s_g[wid] = v; }
                __syncthreads();
                if (tid < 32) {
                    int kk = s_i[tid]; float SS = s_h[tid]; float vv = s_g[tid];
                    #pragma unroll
                    for (int o = 16; o; o >>= 1) {
                        kk += __shfl_xor_sync(0xffffffffu, kk, o);
                        SS += __shfl_xor_sync(0xffffffffu, SS, o);
                        vv  = fmaxf(vv, __shfl_xor_sync(0xffffffffu, vv, o));
                    }
                    if (tid == 0) { s_bK = kk; s_bS = SS; s_bV = vv; }
                }
                __syncthreads();
                const int   K  = s_bK;
                const float Sa = s_bS;
                const float Va = s_bV;
                if (K == kprev || it == 63) {
                    const float vt = (Va > -1e29f) ? Va : 0.0f;
                    tau_ref = (Sa + vt - 1.0f) / (float)K;
                    break;
                }
                kprev = K;
                tau = (Sa - 1.0f) / (float)K;
                __syncthreads();
            }
        }

        // ---- output: relu(z - tau_ref)^1.5 from registers ----
        float4* orow = (float4*)(out + (long long)row * NC);
        #pragma unroll
        for (int j = 0; j < VPT; ++j) {
            const int f = tid + j * TPB;
            if (f < NV) {
                const float4 v = r[j];
                float a = v.x - tau_ref;
                float b = v.y - tau_ref;
                float c = v.z - tau_ref;
                float d = v.w - tau_ref;
                float4 o;
                if (fmaxf(fmaxf(a, b), fmaxf(c, d)) > 0.0f) {
                    a = fmaxf(a, 0.0f); b = fmaxf(b, 0.0f);
                    c = fmaxf(c, 0.0f); d = fmaxf(d, 0.0f);
                    o.x = a * sqrtf(a);
                    o.y = b * sqrtf(b);
                    o.z = c * sqrtf(c);
                    o.w = d * sqrtf(d);
                } else {
                    o.x = 0.0f; o.y = 0.0f; o.z = 0.0f; o.w = 0.0f;
                }
                __stcs(&orow[f], o);
            }
        }
        // next MBAR_WAIT orders us behind the in-flight TMA.
    }
}

extern "C" void kernel_launch(void* const* d_in, const int* in_sizes, int n_in,
                              void* d_out, int out_size) {
    const float* z = (const float*)d_in[0];
    float* out = (float*)d_out;
    const int rows = in_sizes[0] / NC;

    int dev = 0, sms = 148;
    cudaGetDevice(&dev);
    cudaDeviceGetAttribute(&sms, cudaDevAttrMultiProcessorCount, dev);
    cudaFuncSetAttribute(entmax_kernel,
                         cudaFuncAttributeMaxDynamicSharedMemorySize, ROW_BYTES);

    const int grid = (rows < sms) ? rows : sms;
    entmax_kernel<<<grid, TPB, ROW_BYTES>>>(z, out, rows, grid);
}